// round 1
// baseline (speedup 1.0000x reference)
#include <cuda_runtime.h>
#include <float.h>

#define NN 50000
#define EE 800000

// ---------------- scratch (no allocation allowed -> __device__ globals) ----
__device__ float d_feat[(size_t)NN * 256];   // x @ W_fc           [N,H*OUT]
__device__ float d_z[(size_t)NN * 64];       // x @ W_gm + b_gm    [N,MAP]
__device__ float d_el[NN * 4];               // attn_l dot         [N,H]
__device__ float d_er[NN * 4];               // attn_r dot         [N,H]
__device__ float d_gated[(size_t)NN * 64];   // gated head-mean    [N,OUT]
__device__ int   d_deg[NN];
__device__ int   d_cur[NN];
__device__ int   d_rowoff[NN + 1];
__device__ int   d_srt[EE];                  // src ids sorted by dst (CSR)
__device__ int   d_bsum[64];
__device__ int   d_bpre[64];

__device__ __forceinline__ float lrelu(float v) { return v > 0.f ? v : 0.2f * v; }

// ---------------- CSR build ------------------------------------------------
__global__ void k_zero() {
    int i = blockIdx.x * blockDim.x + threadIdx.x;
    if (i < NN) { d_deg[i] = 0; d_cur[i] = 0; }
}

__global__ void k_count(const int* __restrict__ dst) {
    int e = blockIdx.x * blockDim.x + threadIdx.x;
    if (e < EE) atomicAdd(&d_deg[dst[e]], 1);
}

__global__ void k_blocksum() {
    __shared__ int sh[1024];
    int i = blockIdx.x * 1024 + threadIdx.x;
    sh[threadIdx.x] = (i < NN) ? d_deg[i] : 0;
    __syncthreads();
    for (int s = 512; s; s >>= 1) {
        if (threadIdx.x < s) sh[threadIdx.x] += sh[threadIdx.x + s];
        __syncthreads();
    }
    if (threadIdx.x == 0) d_bsum[blockIdx.x] = sh[0];
}

__global__ void k_scanbsum(int nb) {
    if (threadIdx.x == 0) {
        int acc = 0;
        for (int i = 0; i < nb; i++) { d_bpre[i] = acc; acc += d_bsum[i]; }
    }
}

__global__ void k_scanfinal() {
    __shared__ int sh[1024];
    int tid = threadIdx.x;
    int i = blockIdx.x * 1024 + tid;
    int v = (i < NN) ? d_deg[i] : 0;
    sh[tid] = v;
    __syncthreads();
    for (int off = 1; off < 1024; off <<= 1) {
        int t = (tid >= off) ? sh[tid - off] : 0;
        __syncthreads();
        sh[tid] += t;
        __syncthreads();
    }
    if (i < NN) d_rowoff[i] = d_bpre[blockIdx.x] + sh[tid] - v;
    if (i == 0) d_rowoff[NN] = EE;
}

__global__ void k_scatter(const int* __restrict__ src, const int* __restrict__ dst) {
    int e = blockIdx.x * blockDim.x + threadIdx.x;
    if (e < EE) {
        int d = dst[e];
        int p = d_rowoff[d] + atomicAdd(&d_cur[d], 1);
        d_srt[p] = src[e];
    }
}

// ---------------- tiled fp32 GEMM: C = [A1|A2] @ B (+bias) -----------------
// 64x64 tile per block, 256 threads, 4x4 micro-tile, BK=16.
__global__ void k_gemm(const float* __restrict__ A1, int K1,
                       const float* __restrict__ A2, int K2,
                       const float* __restrict__ B,
                       const float* __restrict__ bias,
                       float* __restrict__ C, int M, int Ncols) {
    __shared__ __align__(16) float As[16][68];
    __shared__ __align__(16) float Bs[16][68];
    int t = threadIdx.x;
    int tx = t & 15, ty = t >> 4;
    int m0 = blockIdx.x * 64, n0 = blockIdx.y * 64;
    int K = K1 + K2;
    float acc[4][4] = {};
    int arow = t >> 2;
    int acol4 = (t & 3) * 4;
    int brow = t >> 4;
    int bcol4 = (t & 15) * 4;

    for (int k0 = 0; k0 < K; k0 += 16) {
        float4 av = make_float4(0.f, 0.f, 0.f, 0.f);
        int gm = m0 + arow;
        if (gm < M) {
            if (k0 < K1) av = *(const float4*)(A1 + (size_t)gm * K1 + k0 + acol4);
            else         av = *(const float4*)(A2 + (size_t)gm * K2 + (k0 - K1) + acol4);
        }
        As[acol4 + 0][arow] = av.x;
        As[acol4 + 1][arow] = av.y;
        As[acol4 + 2][arow] = av.z;
        As[acol4 + 3][arow] = av.w;
        float4 bv = *(const float4*)(B + (size_t)(k0 + brow) * Ncols + n0 + bcol4);
        *(float4*)&Bs[brow][bcol4] = bv;
        __syncthreads();
#pragma unroll
        for (int kk = 0; kk < 16; kk++) {
            float4 a = *(const float4*)&As[kk][ty * 4];
            float4 b = *(const float4*)&Bs[kk][tx * 4];
            acc[0][0] += a.x * b.x; acc[0][1] += a.x * b.y; acc[0][2] += a.x * b.z; acc[0][3] += a.x * b.w;
            acc[1][0] += a.y * b.x; acc[1][1] += a.y * b.y; acc[1][2] += a.y * b.z; acc[1][3] += a.y * b.w;
            acc[2][0] += a.z * b.x; acc[2][1] += a.z * b.y; acc[2][2] += a.z * b.z; acc[2][3] += a.z * b.w;
            acc[3][0] += a.w * b.x; acc[3][1] += a.w * b.y; acc[3][2] += a.w * b.z; acc[3][3] += a.w * b.w;
        }
        __syncthreads();
    }
#pragma unroll
    for (int i = 0; i < 4; i++) {
        int gm = m0 + ty * 4 + i;
        if (gm < M) {
#pragma unroll
            for (int j = 0; j < 4; j++) {
                int gn = n0 + tx * 4 + j;
                float v = acc[i][j];
                if (bias) v += bias[gn];
                C[(size_t)gm * Ncols + gn] = v;
            }
        }
    }
}

// ---------------- el / er: per-node head dots ------------------------------
__global__ void k_elr(const float* __restrict__ attn_l, const float* __restrict__ attn_r) {
    int w = (blockIdx.x * blockDim.x + threadIdx.x) >> 5;
    if (w >= NN) return;
    int lane = threadIdx.x & 31;
    const float4* fp = (const float4*)(d_feat + (size_t)w * 256 + lane * 8);
    float4 f0 = fp[0], f1 = fp[1];
    const float4* al = (const float4*)(attn_l + lane * 8);
    const float4* ar = (const float4*)(attn_r + lane * 8);
    float4 a0 = al[0], a1 = al[1];
    float4 r0 = ar[0], r1 = ar[1];
    float sl = f0.x * a0.x + f0.y * a0.y + f0.z * a0.z + f0.w * a0.w
             + f1.x * a1.x + f1.y * a1.y + f1.z * a1.z + f1.w * a1.w;
    float sr = f0.x * r0.x + f0.y * r0.y + f0.z * r0.z + f0.w * r0.w
             + f1.x * r1.x + f1.y * r1.y + f1.z * r1.z + f1.w * r1.w;
#pragma unroll
    for (int o = 1; o < 8; o <<= 1) {
        sl += __shfl_xor_sync(0xffffffffu, sl, o);
        sr += __shfl_xor_sync(0xffffffffu, sr, o);
    }
    if ((lane & 7) == 0) {
        d_el[w * 4 + (lane >> 3)] = sl;
        d_er[w * 4 + (lane >> 3)] = sr;
    }
}

// ---------------- fused aggregation: one warp per dst node -----------------
__global__ void k_agg(const float* __restrict__ x,
                      const float* __restrict__ W_gate,
                      const float* __restrict__ b_gate,
                      const float* __restrict__ b_gat) {
    int w = (blockIdx.x * blockDim.x + threadIdx.x) >> 5;
    if (w >= NN) return;
    int lane = threadIdx.x & 31;
    int beg = d_rowoff[w], end = d_rowoff[w + 1];
    float4 erv = *(const float4*)(d_er + w * 4);
    float er_arr[4] = { erv.x, erv.y, erv.z, erv.w };

    // pass 1: sum x, max z, attention row-max
    float sx0 = 0, sx1 = 0, sx2 = 0, sx3 = 0;
    float mz0 = -FLT_MAX, mz1 = -FLT_MAX;
    float m0 = -FLT_MAX, m1 = -FLT_MAX, m2 = -FLT_MAX, m3 = -FLT_MAX;
    for (int p = beg; p < end; p++) {
        int s = d_srt[p];
        float4 xv = *(const float4*)(x + (size_t)s * 128 + lane * 4);
        sx0 += xv.x; sx1 += xv.y; sx2 += xv.z; sx3 += xv.w;
        float2 zv = *(const float2*)(d_z + (size_t)s * 64 + lane * 2);
        mz0 = fmaxf(mz0, zv.x); mz1 = fmaxf(mz1, zv.y);
        float4 ev = *(const float4*)(d_el + s * 4);
        m0 = fmaxf(m0, lrelu(ev.x + erv.x));
        m1 = fmaxf(m1, lrelu(ev.y + erv.y));
        m2 = fmaxf(m2, lrelu(ev.z + erv.z));
        m3 = fmaxf(m3, lrelu(ev.w + erv.w));
    }

    int h = lane >> 3;
    float mh = h == 0 ? m0 : (h == 1 ? m1 : (h == 2 ? m2 : m3));
    float erh = er_arr[h];

    // pass 2: softmax-weighted feat accumulation (lane covers 8 feat elems of head h)
    float acc[8] = {0, 0, 0, 0, 0, 0, 0, 0};
    float dh = 0.f;
    for (int p = beg; p < end; p++) {
        int s = d_srt[p];
        float elh = __ldg(d_el + s * 4 + h);
        float wgt = __expf(lrelu(elh + erh) - mh);
        dh += wgt;
        const float4* fp = (const float4*)(d_feat + (size_t)s * 256 + lane * 8);
        float4 f0 = fp[0], f1 = fp[1];
        acc[0] += wgt * f0.x; acc[1] += wgt * f0.y; acc[2] += wgt * f0.z; acc[3] += wgt * f0.w;
        acc[4] += wgt * f1.x; acc[5] += wgt * f1.y; acc[6] += wgt * f1.z; acc[7] += wgt * f1.w;
    }

    // finalize: mean_x, max_z fixups, gate MLP (320->4), head gating, mean over heads
    int deg = end - beg;
    float invm = 1.f / (float)(deg > 1 ? deg : 1);
    float mx0 = sx0 * invm, mx1 = sx1 * invm, mx2 = sx2 * invm, mx3 = sx3 * invm;
    if (deg == 0) { mz0 = 0.f; mz1 = 0.f; }

    float4 xv = *(const float4*)(x + (size_t)w * 128 + lane * 4);
    const float4* Wg4 = (const float4*)W_gate;  // W_gate rows are float4 (H=4)
    float t0 = 0, t1 = 0, t2 = 0, t3 = 0;
#define ADDROW(row, val) { float4 ww = __ldg(&Wg4[row]); float vv = (val); \
        t0 += vv * ww.x; t1 += vv * ww.y; t2 += vv * ww.z; t3 += vv * ww.w; }
    ADDROW(4 * lane + 0, xv.x); ADDROW(4 * lane + 1, xv.y);
    ADDROW(4 * lane + 2, xv.z); ADDROW(4 * lane + 3, xv.w);
    ADDROW(128 + 2 * lane + 0, mz0); ADDROW(128 + 2 * lane + 1, mz1);
    ADDROW(192 + 4 * lane + 0, mx0); ADDROW(192 + 4 * lane + 1, mx1);
    ADDROW(192 + 4 * lane + 2, mx2); ADDROW(192 + 4 * lane + 3, mx3);
#undef ADDROW
#pragma unroll
    for (int o = 16; o; o >>= 1) {
        t0 += __shfl_xor_sync(0xffffffffu, t0, o);
        t1 += __shfl_xor_sync(0xffffffffu, t1, o);
        t2 += __shfl_xor_sync(0xffffffffu, t2, o);
        t3 += __shfl_xor_sync(0xffffffffu, t3, o);
    }
    float4 bg = *(const float4*)b_gate;
    float g0 = 1.f / (1.f + __expf(-(t0 + bg.x)));
    float g1 = 1.f / (1.f + __expf(-(t1 + bg.y)));
    float g2 = 1.f / (1.f + __expf(-(t2 + bg.z)));
    float g3 = 1.f / (1.f + __expf(-(t3 + bg.w)));
    float gh = h == 0 ? g0 : (h == 1 ? g1 : (h == 2 ? g2 : g3));

    float invd = dh > 0.f ? 1.f / dh : 0.f;
#pragma unroll
    for (int i = 0; i < 8; i++) {
        float ao = acc[i] * invd + __ldg(b_gat + lane * 8 + i);  // attn_out[h][d]
        float c = gh * ao;
        c += __shfl_xor_sync(0xffffffffu, c, 8);    // sum over head bit 0
        c += __shfl_xor_sync(0xffffffffu, c, 16);   // sum over head bit 1
        if (lane < 8) d_gated[(size_t)w * 64 + lane * 8 + i] = 0.25f * c;
    }
}

// ---------------- launch ----------------------------------------------------
extern "C" void kernel_launch(void* const* d_in, const int* in_sizes, int n_in,
                              void* d_out, int out_size) {
    const float* x       = (const float*)d_in[0];
    const int*   ei      = (const int*)d_in[1];
    const float* W_gm    = (const float*)d_in[2];
    const float* b_gm    = (const float*)d_in[3];
    const float* W_gate  = (const float*)d_in[4];
    const float* b_gate  = (const float*)d_in[5];
    const float* W_fc    = (const float*)d_in[6];
    const float* attn_l  = (const float*)d_in[7];
    const float* attn_r  = (const float*)d_in[8];
    const float* b_gat   = (const float*)d_in[9];
    const float* W_merge = (const float*)d_in[10];
    const float* b_merge = (const float*)d_in[11];
    float* out = (float*)d_out;

    const int* src = ei;
    const int* dst = ei + EE;

    float *feat, *zbuf, *gated;
    cudaGetSymbolAddress((void**)&feat,  d_feat);
    cudaGetSymbolAddress((void**)&zbuf,  d_z);
    cudaGetSymbolAddress((void**)&gated, d_gated);

    const int NB = (NN + 1023) / 1024;  // 49

    // CSR build
    k_zero<<<(NN + 255) / 256, 256>>>();
    k_count<<<(EE + 255) / 256, 256>>>(dst);
    k_blocksum<<<NB, 1024>>>();
    k_scanbsum<<<1, 32>>>(NB);
    k_scanfinal<<<NB, 1024>>>();
    k_scatter<<<(EE + 255) / 256, 256>>>(src, dst);

    // GEMMs
    dim3 gfeat((NN + 63) / 64, 4);
    k_gemm<<<gfeat, 256>>>(x, 128, nullptr, 0, W_fc, nullptr, feat, NN, 256);
    dim3 gz((NN + 63) / 64, 1);
    k_gemm<<<gz, 256>>>(x, 128, nullptr, 0, W_gm, b_gm, zbuf, NN, 64);

    // per-node attention prep + fused aggregation
    int agg_blocks = (NN * 32 + 255) / 256;
    k_elr<<<agg_blocks, 256>>>(attn_l, attn_r);
    k_agg<<<agg_blocks, 256>>>(x, W_gate, b_gate, b_gat);

    // merge: out = [x | gated] @ W_merge + b_merge
    dim3 gm((NN + 63) / 64, 1);
    k_gemm<<<gm, 256>>>(x, 128, gated, 64, W_merge, b_merge, out, NN, 64);
}

// round 4
// speedup vs baseline: 1.1875x; 1.1875x over previous
#include <cuda_runtime.h>
#include <float.h>

#define NN 50000
#define EE 800000

// ---------------- scratch (no allocation allowed -> __device__ globals) ----
__device__ float d_feat[(size_t)NN * 256];   // x @ W_fc           [N,H*OUT]
__device__ float d_z[(size_t)NN * 64];       // x @ W_gm + b_gm    [N,MAP]
__device__ float d_el[NN * 4];               // attn_l dot         [N,H]
__device__ float d_er[NN * 4];               // attn_r dot         [N,H]
__device__ float d_gs[NN * 4];               // x @ W_gate[0:128]  [N,H]
__device__ float d_gmn[NN * 4];              // x @ W_gate[192:]   [N,H]
__device__ float d_gated[(size_t)NN * 64];   // gated head-mean    [N,OUT]
__device__ int   d_deg[NN];
__device__ int   d_cur[NN];
__device__ int   d_rowoff[NN + 1];
__device__ int   d_srt[EE];                  // src ids sorted by dst (CSR)
__device__ int   d_bsum[64];
__device__ int   d_bpre[64];

__device__ __forceinline__ float lrelu(float v) { return v > 0.f ? v : 0.2f * v; }

// ---------------- CSR build ------------------------------------------------
__global__ void k_zero() {
    int i = blockIdx.x * blockDim.x + threadIdx.x;
    if (i < NN) { d_deg[i] = 0; d_cur[i] = 0; }
}

__global__ void k_count(const int* __restrict__ dst) {
    int e = blockIdx.x * blockDim.x + threadIdx.x;
    if (e < EE) atomicAdd(&d_deg[dst[e]], 1);
}

__global__ void k_blocksum() {
    __shared__ int sh[1024];
    int i = blockIdx.x * 1024 + threadIdx.x;
    sh[threadIdx.x] = (i < NN) ? d_deg[i] : 0;
    __syncthreads();
    for (int s = 512; s; s >>= 1) {
        if (threadIdx.x < s) sh[threadIdx.x] += sh[threadIdx.x + s];
        __syncthreads();
    }
    if (threadIdx.x == 0) d_bsum[blockIdx.x] = sh[0];
}

__global__ void k_scanbsum(int nb) {
    __shared__ int sh[64];
    int t = threadIdx.x;
    int v = (t < nb) ? d_bsum[t] : 0;
    sh[t] = v;
    __syncthreads();
    for (int o = 1; o < 64; o <<= 1) {
        int u = (t >= o) ? sh[t - o] : 0;
        __syncthreads();
        sh[t] += u;
        __syncthreads();
    }
    if (t < nb) d_bpre[t] = sh[t] - v;
}

__global__ void k_scanfinal() {
    __shared__ int sh[1024];
    int tid = threadIdx.x;
    int i = blockIdx.x * 1024 + tid;
    int v = (i < NN) ? d_deg[i] : 0;
    sh[tid] = v;
    __syncthreads();
    for (int off = 1; off < 1024; off <<= 1) {
        int t = (tid >= off) ? sh[tid - off] : 0;
        __syncthreads();
        sh[tid] += t;
        __syncthreads();
    }
    if (i < NN) d_rowoff[i] = d_bpre[blockIdx.x] + sh[tid] - v;
    if (i == 0) d_rowoff[NN] = EE;
}

__global__ void k_scatter(const int* __restrict__ src, const int* __restrict__ dst) {
    int e = blockIdx.x * blockDim.x + threadIdx.x;
    if (e < EE) {
        int d = dst[e];
        int p = d_rowoff[d] + atomicAdd(&d_cur[d], 1);
        d_srt[p] = src[e];
    }
}

// ---------------- tiled fp32 GEMM: C = [A1|A2] @ B (+bias) -----------------
// BMxBN block tile, 256 threads, TMxTN micro-tile, BK=16. FFMA-bound config.
template<int BM, int BN, int TM, int TN>
__global__ void k_gemm(const float* __restrict__ A1, int K1,
                       const float* __restrict__ A2, int K2,
                       const float* __restrict__ B,
                       const float* __restrict__ bias,
                       float* __restrict__ C, int M, int Ncols) {
    constexpr int BK = 16;
    constexpr int NTH = (BM / TM) * (BN / TN);   // must be 256
    __shared__ __align__(16) float As[BK][BM + 4];
    __shared__ __align__(16) float Bs[BK][BN + 4];
    int t = threadIdx.x;
    int tx = t % (BN / TN);
    int ty = t / (BN / TN);
    int m0 = blockIdx.x * BM, n0 = blockIdx.y * BN;
    int K = K1 + K2;
    float acc[TM][TN] = {};

    for (int k0 = 0; k0 < K; k0 += BK) {
        // load A tile (BM x BK), store transposed As[k][m]
#pragma unroll
        for (int l = 0; l < BM * BK / 4 / NTH; l++) {
            int fidx = t + l * NTH;
            int row = fidx / (BK / 4);
            int c4  = (fidx % (BK / 4)) * 4;
            int gm = m0 + row;
            int k = k0 + c4;
            float4 av = make_float4(0.f, 0.f, 0.f, 0.f);
            if (gm < M) {
                if (k < K1) av = *(const float4*)(A1 + (size_t)gm * K1 + k);
                else        av = *(const float4*)(A2 + (size_t)gm * K2 + (k - K1));
            }
            As[c4 + 0][row] = av.x;
            As[c4 + 1][row] = av.y;
            As[c4 + 2][row] = av.z;
            As[c4 + 3][row] = av.w;
        }
        // load B tile (BK x BN), row-major
#pragma unroll
        for (int l = 0; l < BK * BN / 4 / NTH; l++) {
            int fidx = t + l * NTH;
            int brow = fidx / (BN / 4);
            int bc4  = (fidx % (BN / 4)) * 4;
            *(float4*)&Bs[brow][bc4] =
                *(const float4*)(B + (size_t)(k0 + brow) * Ncols + n0 + bc4);
        }
        __syncthreads();
#pragma unroll
        for (int kk = 0; kk < BK; kk++) {
            float af[TM], bf[TN];
#pragma unroll
            for (int i = 0; i < TM; i += 4)
                *(float4*)&af[i] = *(const float4*)&As[kk][ty * TM + i];
#pragma unroll
            for (int j = 0; j < TN; j += 4)
                *(float4*)&bf[j] = *(const float4*)&Bs[kk][tx * TN + j];
#pragma unroll
            for (int i = 0; i < TM; i++)
#pragma unroll
                for (int j = 0; j < TN; j++)
                    acc[i][j] += af[i] * bf[j];
        }
        __syncthreads();
    }
#pragma unroll
    for (int i = 0; i < TM; i++) {
        int gm = m0 + ty * TM + i;
        if (gm < M) {
#pragma unroll
            for (int j = 0; j < TN; j += 4) {
                int gn = n0 + tx * TN + j;
                float4 v = *(float4*)&acc[i][j];
                if (bias) {
                    v.x += bias[gn + 0]; v.y += bias[gn + 1];
                    v.z += bias[gn + 2]; v.w += bias[gn + 3];
                }
                *(float4*)(C + (size_t)gm * Ncols + gn) = v;
            }
        }
    }
}

// ---------------- el / er: per-node head dots ------------------------------
__global__ void k_elr(const float* __restrict__ attn_l, const float* __restrict__ attn_r) {
    int w = (blockIdx.x * blockDim.x + threadIdx.x) >> 5;
    if (w >= NN) return;
    int lane = threadIdx.x & 31;
    const float4* fp = (const float4*)(d_feat + (size_t)w * 256 + lane * 8);
    float4 f0 = fp[0], f1 = fp[1];
    const float4* al = (const float4*)(attn_l + lane * 8);
    const float4* ar = (const float4*)(attn_r + lane * 8);
    float4 a0 = al[0], a1 = al[1];
    float4 r0 = ar[0], r1 = ar[1];
    float sl = f0.x * a0.x + f0.y * a0.y + f0.z * a0.z + f0.w * a0.w
             + f1.x * a1.x + f1.y * a1.y + f1.z * a1.z + f1.w * a1.w;
    float sr = f0.x * r0.x + f0.y * r0.y + f0.z * r0.z + f0.w * r0.w
             + f1.x * r1.x + f1.y * r1.y + f1.z * r1.z + f1.w * r1.w;
#pragma unroll
    for (int o = 1; o < 8; o <<= 1) {
        sl += __shfl_xor_sync(0xffffffffu, sl, o);
        sr += __shfl_xor_sync(0xffffffffu, sr, o);
    }
    if ((lane & 7) == 0) {
        d_el[w * 4 + (lane >> 3)] = sl;
        d_er[w * 4 + (lane >> 3)] = sr;
    }
}

// ---------------- per-node gate pre-projection -----------------------------
// g_self = x @ W_gate[0:128], g_mean = x @ W_gate[192:320]   (both [N,4])
__global__ void k_xg(const float* __restrict__ x, const float* __restrict__ W_gate) {
    int w = (blockIdx.x * blockDim.x + threadIdx.x) >> 5;
    if (w >= NN) return;
    int lane = threadIdx.x & 31;
    float4 xv = *(const float4*)(x + (size_t)w * 128 + lane * 4);
    const float4* Wg4 = (const float4*)W_gate;
    float s0 = 0, s1 = 0, s2 = 0, s3 = 0;
    float q0 = 0, q1 = 0, q2 = 0, q3 = 0;
    float xa[4] = { xv.x, xv.y, xv.z, xv.w };
#pragma unroll
    for (int i = 0; i < 4; i++) {
        float4 ws = __ldg(&Wg4[lane * 4 + i]);
        float4 wm = __ldg(&Wg4[192 + lane * 4 + i]);
        s0 += xa[i] * ws.x; s1 += xa[i] * ws.y; s2 += xa[i] * ws.z; s3 += xa[i] * ws.w;
        q0 += xa[i] * wm.x; q1 += xa[i] * wm.y; q2 += xa[i] * wm.z; q3 += xa[i] * wm.w;
    }
#pragma unroll
    for (int o = 16; o; o >>= 1) {
        s0 += __shfl_xor_sync(0xffffffffu, s0, o);
        s1 += __shfl_xor_sync(0xffffffffu, s1, o);
        s2 += __shfl_xor_sync(0xffffffffu, s2, o);
        s3 += __shfl_xor_sync(0xffffffffu, s3, o);
        q0 += __shfl_xor_sync(0xffffffffu, q0, o);
        q1 += __shfl_xor_sync(0xffffffffu, q1, o);
        q2 += __shfl_xor_sync(0xffffffffu, q2, o);
        q3 += __shfl_xor_sync(0xffffffffu, q3, o);
    }
    if (lane == 0) {
        *(float4*)(d_gs  + w * 4) = make_float4(s0, s1, s2, s3);
        *(float4*)(d_gmn + w * 4) = make_float4(q0, q1, q2, q3);
    }
}

// ---------------- fused single-pass aggregation: one warp per dst ----------
__global__ void k_agg(const float* __restrict__ W_gate,
                      const float* __restrict__ b_gate,
                      const float* __restrict__ b_gat) {
    int w = (blockIdx.x * blockDim.x + threadIdx.x) >> 5;
    if (w >= NN) return;
    int lane = threadIdx.x & 31;
    int h = lane >> 3;
    int beg = d_rowoff[w], end = d_rowoff[w + 1];
    float erh = __ldg(d_er + w * 4 + h);

    float mz0 = -FLT_MAX, mz1 = -FLT_MAX;        // max z (2 dims/lane)
    float sg0 = 0, sg1 = 0, sg2 = 0, sg3 = 0;    // sum g_mean (uniform)
    float mh = -FLT_MAX, dh = 0.f;               // online softmax state
    float a0 = 0, a1 = 0, a2 = 0, a3 = 0, a4 = 0, a5 = 0, a6 = 0, a7 = 0;

    // software-pipelined index: s for iteration p resolves during p-1's gathers
    int s = (beg < end) ? __ldg(d_srt + beg) : 0;
    for (int p = beg; p < end; p++) {
        int s_next = (p + 1 < end) ? __ldg(d_srt + p + 1) : 0;
        float2 zv = *(const float2*)(d_z + (size_t)s * 64 + lane * 2);
        float4 gv = __ldg((const float4*)(d_gmn + s * 4));
        float elh = __ldg(d_el + s * 4 + h);
        const float4* fp = (const float4*)(d_feat + (size_t)s * 256 + lane * 8);
        float4 f0 = fp[0], f1 = fp[1];

        mz0 = fmaxf(mz0, zv.x); mz1 = fmaxf(mz1, zv.y);
        sg0 += gv.x; sg1 += gv.y; sg2 += gv.z; sg3 += gv.w;
        float e = lrelu(elh + erh);
        float mnew = fmaxf(mh, e);
        float corr = __expf(mh - mnew);
        float wgt  = __expf(e - mnew);
        mh = mnew;
        dh = dh * corr + wgt;
        a0 = a0 * corr + wgt * f0.x; a1 = a1 * corr + wgt * f0.y;
        a2 = a2 * corr + wgt * f0.z; a3 = a3 * corr + wgt * f0.w;
        a4 = a4 * corr + wgt * f1.x; a5 = a5 * corr + wgt * f1.y;
        a6 = a6 * corr + wgt * f1.z; a7 = a7 * corr + wgt * f1.w;
        s = s_next;
    }

    int deg = end - beg;
    if (deg == 0) { mz0 = 0.f; mz1 = 0.f; }
    float invm = 1.f / (float)(deg > 1 ? deg : 1);

    // gate logits: max_z contribution (reduce over lanes) + precomputed parts
    const float4* Wg4 = (const float4*)W_gate;
    float4 wz0 = __ldg(&Wg4[128 + 2 * lane]);
    float4 wz1 = __ldg(&Wg4[129 + 2 * lane]);
    float t0 = mz0 * wz0.x + mz1 * wz1.x;
    float t1 = mz0 * wz0.y + mz1 * wz1.y;
    float t2 = mz0 * wz0.z + mz1 * wz1.z;
    float t3 = mz0 * wz0.w + mz1 * wz1.w;
#pragma unroll
    for (int o = 16; o; o >>= 1) {
        t0 += __shfl_xor_sync(0xffffffffu, t0, o);
        t1 += __shfl_xor_sync(0xffffffffu, t1, o);
        t2 += __shfl_xor_sync(0xffffffffu, t2, o);
        t3 += __shfl_xor_sync(0xffffffffu, t3, o);
    }
    float4 gsv = *(const float4*)(d_gs + w * 4);
    float4 bg  = *(const float4*)b_gate;
    t0 += gsv.x + sg0 * invm + bg.x;
    t1 += gsv.y + sg1 * invm + bg.y;
    t2 += gsv.z + sg2 * invm + bg.z;
    t3 += gsv.w + sg3 * invm + bg.w;
    float g0 = 1.f / (1.f + __expf(-t0));
    float g1 = 1.f / (1.f + __expf(-t1));
    float g2 = 1.f / (1.f + __expf(-t2));
    float g3 = 1.f / (1.f + __expf(-t3));
    float gh = h == 0 ? g0 : (h == 1 ? g1 : (h == 2 ? g2 : g3));

    float invd = dh > 0.f ? 1.f / dh : 0.f;
    float accs[8] = { a0, a1, a2, a3, a4, a5, a6, a7 };
#pragma unroll
    for (int i = 0; i < 8; i++) {
        float ao = accs[i] * invd + __ldg(b_gat + lane * 8 + i);
        float c = gh * ao;
        c += __shfl_xor_sync(0xffffffffu, c, 8);
        c += __shfl_xor_sync(0xffffffffu, c, 16);
        if (lane < 8) d_gated[(size_t)w * 64 + lane * 8 + i] = 0.25f * c;
    }
}

// ---------------- launch ----------------------------------------------------
extern "C" void kernel_launch(void* const* d_in, const int* in_sizes, int n_in,
                              void* d_out, int out_size) {
    const float* x       = (const float*)d_in[0];
    const int*   ei      = (const int*)d_in[1];
    const float* W_gm    = (const float*)d_in[2];
    const float* b_gm    = (const float*)d_in[3];
    const float* W_gate  = (const float*)d_in[4];
    const float* b_gate  = (const float*)d_in[5];
    const float* W_fc    = (const float*)d_in[6];
    const float* attn_l  = (const float*)d_in[7];
    const float* attn_r  = (const float*)d_in[8];
    const float* b_gat   = (const float*)d_in[9];
    const float* W_merge = (const float*)d_in[10];
    const float* b_merge = (const float*)d_in[11];
    float* out = (float*)d_out;

    const int* src = ei;
    const int* dst = ei + EE;

    float *feat, *zbuf, *gated;
    cudaGetSymbolAddress((void**)&feat,  d_feat);
    cudaGetSymbolAddress((void**)&zbuf,  d_z);
    cudaGetSymbolAddress((void**)&gated, d_gated);

    const int NB = (NN + 1023) / 1024;  // 49
    int warp_blocks = (NN * 32 + 255) / 256;

    // launches 0-4: CSR prefix
    k_zero<<<(NN + 255) / 256, 256>>>();
    k_count<<<(EE + 255) / 256, 256>>>(dst);
    k_blocksum<<<NB, 1024>>>();
    k_scanbsum<<<1, 64>>>(NB);
    k_scanfinal<<<NB, 1024>>>();

    // launch 5 (ncu -s 5 -c 1 captures this): the big feat GEMM
    dim3 gfeat((NN + 127) / 128, 2);
    k_gemm<128, 128, 8, 8><<<gfeat, 256>>>(x, 128, nullptr, 0, W_fc, nullptr, feat, NN, 256);

    k_scatter<<<(EE + 255) / 256, 256>>>(src, dst);

    dim3 gz((NN + 127) / 128, 1);
    k_gemm<128, 64, 8, 4><<<gz, 256>>>(x, 128, nullptr, 0, W_gm, b_gm, zbuf, NN, 64);

    k_elr<<<warp_blocks, 256>>>(attn_l, attn_r);
    k_xg<<<warp_blocks, 256>>>(x, W_gate);
    k_agg<<<warp_blocks, 256>>>(W_gate, b_gate, b_gat);

    dim3 gm((NN + 127) / 128, 1);
    k_gemm<128, 64, 8, 4><<<gm, 256>>>(x, 128, gated, 64, W_merge, b_merge, out, NN, 64);
}

// round 5
// speedup vs baseline: 1.2095x; 1.0185x over previous
#include <cuda_runtime.h>
#include <float.h>

#define NN 50000
#define EE 800000

// ---------------- scratch (no allocation allowed -> __device__ globals) ----
__device__ float d_feat[(size_t)NN * 256];   // x @ W_fc           [N,H*OUT]
__device__ float d_z[(size_t)NN * 64];       // x @ W_gm + b_gm    [N,MAP]
__device__ float d_el[NN * 4];               // attn_l dot         [N,H]
__device__ float d_er[NN * 4];               // attn_r dot         [N,H]
__device__ float d_gs[NN * 4];               // x @ W_gate[0:128]  [N,H]
__device__ float d_gmn[NN * 4];              // x @ W_gate[192:]   [N,H]
__device__ float d_gated[(size_t)NN * 64];   // gated head-mean    [N,OUT]
__device__ int   d_deg[NN];
__device__ int   d_cur[NN];
__device__ int   d_rowoff[NN + 1];
__device__ int   d_srt[EE];                  // src ids sorted by dst (CSR)
__device__ int   d_bsum[64];
__device__ int   d_bpre[64];

__device__ __forceinline__ float lrelu(float v) { return v > 0.f ? v : 0.2f * v; }

#define PACK2(out, lo, hi) \
    asm("mov.b64 %0, {%1, %2};" : "=l"(out) : "r"(__float_as_uint(lo)), "r"(__float_as_uint(hi)))
#define UNPACK2(lo, hi, in) \
    do { unsigned _ulo, _uhi; \
         asm("mov.b64 {%0, %1}, %2;" : "=r"(_ulo), "=r"(_uhi) : "l"(in)); \
         lo = __uint_as_float(_ulo); hi = __uint_as_float(_uhi); } while (0)
#define FMA2(acc, a, b) \
    asm("fma.rn.f32x2 %0, %1, %2, %0;" : "+l"(acc) : "l"(a), "l"(b))

// ---------------- CSR build ------------------------------------------------
__global__ void k_count(const int* __restrict__ dst) {
    int e = blockIdx.x * blockDim.x + threadIdx.x;
    if (e < EE) atomicAdd(&d_deg[dst[e]], 1);
}

__global__ void k_blocksum() {
    __shared__ int sh[1024];
    int i = blockIdx.x * 1024 + threadIdx.x;
    sh[threadIdx.x] = (i < NN) ? d_deg[i] : 0;
    __syncthreads();
    for (int s = 512; s; s >>= 1) {
        if (threadIdx.x < s) sh[threadIdx.x] += sh[threadIdx.x + s];
        __syncthreads();
    }
    if (threadIdx.x == 0) d_bsum[blockIdx.x] = sh[0];
}

__global__ void k_scanbsum(int nb) {
    __shared__ int sh[64];
    int t = threadIdx.x;
    int v = (t < nb) ? d_bsum[t] : 0;
    sh[t] = v;
    __syncthreads();
    for (int o = 1; o < 64; o <<= 1) {
        int u = (t >= o) ? sh[t - o] : 0;
        __syncthreads();
        sh[t] += u;
        __syncthreads();
    }
    if (t < nb) d_bpre[t] = sh[t] - v;
}

__global__ void k_scanfinal() {
    __shared__ int sh[1024];
    int tid = threadIdx.x;
    int i = blockIdx.x * 1024 + tid;
    int v = (i < NN) ? d_deg[i] : 0;
    sh[tid] = v;
    __syncthreads();
    for (int off = 1; off < 1024; off <<= 1) {
        int t = (tid >= off) ? sh[tid - off] : 0;
        __syncthreads();
        sh[tid] += t;
        __syncthreads();
    }
    if (i < NN) d_rowoff[i] = d_bpre[blockIdx.x] + sh[tid] - v;
    if (i == 0) d_rowoff[NN] = EE;
}

__global__ void k_scatter(const int* __restrict__ src, const int* __restrict__ dst) {
    int e = blockIdx.x * blockDim.x + threadIdx.x;
    if (e < EE) {
        int d = dst[e];
        int p = d_rowoff[d] + atomicAdd(&d_cur[d], 1);
        d_srt[p] = src[e];
    }
}

// ---------------- tiled fp32 GEMM with packed FFMA2 ------------------------
// BMxBN block tile, 256 threads, TMxTN micro-tile, BK=16.
template<int BM, int BN, int TM, int TN>
__global__ void k_gemm(const float* __restrict__ A1, int K1,
                       const float* __restrict__ A2, int K2,
                       const float* __restrict__ B,
                       const float* __restrict__ bias,
                       float* __restrict__ C, int M, int Ncols) {
    constexpr int BK = 16;
    constexpr int NTH = (BM / TM) * (BN / TN);   // must be 256
    __shared__ __align__(16) float As[BK][BM + 4];
    __shared__ __align__(16) float Bs[BK][BN + 4];
    int t = threadIdx.x;
    int tx = t % (BN / TN);
    int ty = t / (BN / TN);
    int m0 = blockIdx.x * BM, n0 = blockIdx.y * BN;
    int K = K1 + K2;
    unsigned long long acc2[TM][TN / 2] = {};   // packed f32x2 accumulators

    for (int k0 = 0; k0 < K; k0 += BK) {
#pragma unroll
        for (int l = 0; l < BM * BK / 4 / NTH; l++) {
            int fidx = t + l * NTH;
            int row = fidx / (BK / 4);
            int c4  = (fidx % (BK / 4)) * 4;
            int gm = m0 + row;
            int k = k0 + c4;
            float4 av = make_float4(0.f, 0.f, 0.f, 0.f);
            if (gm < M) {
                if (k < K1) av = *(const float4*)(A1 + (size_t)gm * K1 + k);
                else        av = *(const float4*)(A2 + (size_t)gm * K2 + (k - K1));
            }
            As[c4 + 0][row] = av.x;
            As[c4 + 1][row] = av.y;
            As[c4 + 2][row] = av.z;
            As[c4 + 3][row] = av.w;
        }
#pragma unroll
        for (int l = 0; l < BK * BN / 4 / NTH; l++) {
            int fidx = t + l * NTH;
            int brow = fidx / (BN / 4);
            int bc4  = (fidx % (BN / 4)) * 4;
            *(float4*)&Bs[brow][bc4] =
                *(const float4*)(B + (size_t)(k0 + brow) * Ncols + n0 + bc4);
        }
        __syncthreads();
#pragma unroll
        for (int kk = 0; kk < BK; kk++) {
            float af[TM], bf[TN];
#pragma unroll
            for (int i = 0; i < TM; i += 4)
                *(float4*)&af[i] = *(const float4*)&As[kk][ty * TM + i];
#pragma unroll
            for (int j = 0; j < TN; j += 4)
                *(float4*)&bf[j] = *(const float4*)&Bs[kk][tx * TN + j];
            unsigned long long bb[TN / 2];
#pragma unroll
            for (int j = 0; j < TN / 2; j++) PACK2(bb[j], bf[2 * j], bf[2 * j + 1]);
#pragma unroll
            for (int i = 0; i < TM; i++) {
                unsigned long long aa;
                PACK2(aa, af[i], af[i]);
#pragma unroll
                for (int j = 0; j < TN / 2; j++) FMA2(acc2[i][j], aa, bb[j]);
            }
        }
        __syncthreads();
    }
#pragma unroll
    for (int i = 0; i < TM; i++) {
        int gm = m0 + ty * TM + i;
        if (gm < M) {
#pragma unroll
            for (int j = 0; j < TN; j += 4) {
                int gn = n0 + tx * TN + j;
                float4 v;
                UNPACK2(v.x, v.y, acc2[i][j / 2]);
                UNPACK2(v.z, v.w, acc2[i][j / 2 + 1]);
                if (bias) {
                    v.x += bias[gn + 0]; v.y += bias[gn + 1];
                    v.z += bias[gn + 2]; v.w += bias[gn + 3];
                }
                *(float4*)(C + (size_t)gm * Ncols + gn) = v;
            }
        }
    }
}

// ---------------- per-node prep: el/er dots + gate pre-projection ----------
// el/er from feat; g_self = x@W_gate[0:128], g_mean = x@W_gate[192:320]
__global__ void k_node(const float* __restrict__ x,
                       const float* __restrict__ attn_l,
                       const float* __restrict__ attn_r,
                       const float* __restrict__ W_gate) {
    int w = (blockIdx.x * blockDim.x + threadIdx.x) >> 5;
    if (w >= NN) return;
    int lane = threadIdx.x & 31;

    // --- el/er: per-head dots over feat ---
    const float4* fp = (const float4*)(d_feat + (size_t)w * 256 + lane * 8);
    float4 f0 = fp[0], f1 = fp[1];
    const float4* al = (const float4*)(attn_l + lane * 8);
    const float4* ar = (const float4*)(attn_r + lane * 8);
    float4 a0 = al[0], a1 = al[1];
    float4 r0 = ar[0], r1 = ar[1];
    float sl = f0.x * a0.x + f0.y * a0.y + f0.z * a0.z + f0.w * a0.w
             + f1.x * a1.x + f1.y * a1.y + f1.z * a1.z + f1.w * a1.w;
    float sr = f0.x * r0.x + f0.y * r0.y + f0.z * r0.z + f0.w * r0.w
             + f1.x * r1.x + f1.y * r1.y + f1.z * r1.z + f1.w * r1.w;
#pragma unroll
    for (int o = 1; o < 8; o <<= 1) {
        sl += __shfl_xor_sync(0xffffffffu, sl, o);
        sr += __shfl_xor_sync(0xffffffffu, sr, o);
    }
    if ((lane & 7) == 0) {
        d_el[w * 4 + (lane >> 3)] = sl;
        d_er[w * 4 + (lane >> 3)] = sr;
    }

    // --- gate pre-projection ---
    float4 xv = *(const float4*)(x + (size_t)w * 128 + lane * 4);
    const float4* Wg4 = (const float4*)W_gate;
    float s0 = 0, s1 = 0, s2 = 0, s3 = 0;
    float q0 = 0, q1 = 0, q2 = 0, q3 = 0;
    float xa[4] = { xv.x, xv.y, xv.z, xv.w };
#pragma unroll
    for (int i = 0; i < 4; i++) {
        float4 ws = __ldg(&Wg4[lane * 4 + i]);
        float4 wm = __ldg(&Wg4[192 + lane * 4 + i]);
        s0 += xa[i] * ws.x; s1 += xa[i] * ws.y; s2 += xa[i] * ws.z; s3 += xa[i] * ws.w;
        q0 += xa[i] * wm.x; q1 += xa[i] * wm.y; q2 += xa[i] * wm.z; q3 += xa[i] * wm.w;
    }
#pragma unroll
    for (int o = 16; o; o >>= 1) {
        s0 += __shfl_xor_sync(0xffffffffu, s0, o);
        s1 += __shfl_xor_sync(0xffffffffu, s1, o);
        s2 += __shfl_xor_sync(0xffffffffu, s2, o);
        s3 += __shfl_xor_sync(0xffffffffu, s3, o);
        q0 += __shfl_xor_sync(0xffffffffu, q0, o);
        q1 += __shfl_xor_sync(0xffffffffu, q1, o);
        q2 += __shfl_xor_sync(0xffffffffu, q2, o);
        q3 += __shfl_xor_sync(0xffffffffu, q3, o);
    }
    if (lane == 0) {
        *(float4*)(d_gs  + w * 4) = make_float4(s0, s1, s2, s3);
        *(float4*)(d_gmn + w * 4) = make_float4(q0, q1, q2, q3);
    }
}

// ---------------- fused single-pass aggregation: one warp per dst ----------
__global__ void k_agg(const float* __restrict__ W_gate,
                      const float* __restrict__ b_gate,
                      const float* __restrict__ b_gat) {
    int w = (blockIdx.x * blockDim.x + threadIdx.x) >> 5;
    if (w >= NN) return;
    int lane = threadIdx.x & 31;
    int h = lane >> 3;
    int beg = d_rowoff[w], end = d_rowoff[w + 1];
    float erh = __ldg(d_er + w * 4 + h);

    float mz0 = -FLT_MAX, mz1 = -FLT_MAX;        // max z (2 dims/lane)
    float sg0 = 0, sg1 = 0, sg2 = 0, sg3 = 0;    // sum g_mean (uniform)
    float mh = -FLT_MAX, dh = 0.f;               // online softmax state
    float a0 = 0, a1 = 0, a2 = 0, a3 = 0, a4 = 0, a5 = 0, a6 = 0, a7 = 0;

    // software-pipelined index: s for iteration p resolves during p-1's gathers
    int s = (beg < end) ? __ldg(d_srt + beg) : 0;
    for (int p = beg; p < end; p++) {
        int s_next = (p + 1 < end) ? __ldg(d_srt + p + 1) : 0;
        float2 zv = *(const float2*)(d_z + (size_t)s * 64 + lane * 2);
        float4 gv = __ldg((const float4*)(d_gmn + s * 4));
        float elh = __ldg(d_el + s * 4 + h);
        const float4* fp = (const float4*)(d_feat + (size_t)s * 256 + lane * 8);
        float4 f0 = fp[0], f1 = fp[1];

        mz0 = fmaxf(mz0, zv.x); mz1 = fmaxf(mz1, zv.y);
        sg0 += gv.x; sg1 += gv.y; sg2 += gv.z; sg3 += gv.w;
        float e = lrelu(elh + erh);
        float mnew = fmaxf(mh, e);
        float corr = __expf(mh - mnew);
        float wgt  = __expf(e - mnew);
        mh = mnew;
        dh = dh * corr + wgt;
        a0 = a0 * corr + wgt * f0.x; a1 = a1 * corr + wgt * f0.y;
        a2 = a2 * corr + wgt * f0.z; a3 = a3 * corr + wgt * f0.w;
        a4 = a4 * corr + wgt * f1.x; a5 = a5 * corr + wgt * f1.y;
        a6 = a6 * corr + wgt * f1.z; a7 = a7 * corr + wgt * f1.w;
        s = s_next;
    }

    int deg = end - beg;
    if (deg == 0) { mz0 = 0.f; mz1 = 0.f; }
    float invm = 1.f / (float)(deg > 1 ? deg : 1);

    const float4* Wg4 = (const float4*)W_gate;
    float4 wz0 = __ldg(&Wg4[128 + 2 * lane]);
    float4 wz1 = __ldg(&Wg4[129 + 2 * lane]);
    float t0 = mz0 * wz0.x + mz1 * wz1.x;
    float t1 = mz0 * wz0.y + mz1 * wz1.y;
    float t2 = mz0 * wz0.z + mz1 * wz1.z;
    float t3 = mz0 * wz0.w + mz1 * wz1.w;
#pragma unroll
    for (int o = 16; o; o >>= 1) {
        t0 += __shfl_xor_sync(0xffffffffu, t0, o);
        t1 += __shfl_xor_sync(0xffffffffu, t1, o);
        t2 += __shfl_xor_sync(0xffffffffu, t2, o);
        t3 += __shfl_xor_sync(0xffffffffu, t3, o);
    }
    float4 gsv = *(const float4*)(d_gs + w * 4);
    float4 bg  = *(const float4*)b_gate;
    t0 += gsv.x + sg0 * invm + bg.x;
    t1 += gsv.y + sg1 * invm + bg.y;
    t2 += gsv.z + sg2 * invm + bg.z;
    t3 += gsv.w + sg3 * invm + bg.w;
    float g0 = 1.f / (1.f + __expf(-t0));
    float g1 = 1.f / (1.f + __expf(-t1));
    float g2 = 1.f / (1.f + __expf(-t2));
    float g3 = 1.f / (1.f + __expf(-t3));
    float gh = h == 0 ? g0 : (h == 1 ? g1 : (h == 2 ? g2 : g3));

    float invd = dh > 0.f ? 1.f / dh : 0.f;
    float accs[8] = { a0, a1, a2, a3, a4, a5, a6, a7 };
#pragma unroll
    for (int i = 0; i < 8; i++) {
        float ao = accs[i] * invd + __ldg(b_gat + lane * 8 + i);
        float c = gh * ao;
        c += __shfl_xor_sync(0xffffffffu, c, 8);
        c += __shfl_xor_sync(0xffffffffu, c, 16);
        if (lane < 8) d_gated[(size_t)w * 64 + lane * 8 + i] = 0.25f * c;
    }
}

// ---------------- launch ----------------------------------------------------
extern "C" void kernel_launch(void* const* d_in, const int* in_sizes, int n_in,
                              void* d_out, int out_size) {
    const float* x       = (const float*)d_in[0];
    const int*   ei      = (const int*)d_in[1];
    const float* W_gm    = (const float*)d_in[2];
    const float* b_gm    = (const float*)d_in[3];
    const float* W_gate  = (const float*)d_in[4];
    const float* b_gate  = (const float*)d_in[5];
    const float* W_fc    = (const float*)d_in[6];
    const float* attn_l  = (const float*)d_in[7];
    const float* attn_r  = (const float*)d_in[8];
    const float* b_gat   = (const float*)d_in[9];
    const float* W_merge = (const float*)d_in[10];
    const float* b_merge = (const float*)d_in[11];
    float* out = (float*)d_out;

    const int* src = ei;
    const int* dst = ei + EE;

    float *feat, *zbuf, *gated;
    int *degp, *curp;
    cudaGetSymbolAddress((void**)&feat,  d_feat);
    cudaGetSymbolAddress((void**)&zbuf,  d_z);
    cudaGetSymbolAddress((void**)&gated, d_gated);
    cudaGetSymbolAddress((void**)&degp,  d_deg);
    cudaGetSymbolAddress((void**)&curp,  d_cur);

    const int NB = (NN + 1023) / 1024;  // 49
    int warp_blocks = (NN * 32 + 255) / 256;

    // CSR prefix (memsets replace k_zero)
    cudaMemsetAsync(degp, 0, NN * sizeof(int));
    cudaMemsetAsync(curp, 0, NN * sizeof(int));
    k_count<<<(EE + 255) / 256, 256>>>(dst);
    k_blocksum<<<NB, 1024>>>();
    k_scanbsum<<<1, 64>>>(NB);
    k_scanfinal<<<NB, 1024>>>();

    // big feat GEMM
    dim3 gfeat((NN + 127) / 128, 2);
    k_gemm<128, 128, 8, 8><<<gfeat, 256>>>(x, 128, nullptr, 0, W_fc, nullptr, feat, NN, 256);

    k_scatter<<<(EE + 255) / 256, 256>>>(src, dst);

    dim3 gz((NN + 127) / 128, 1);
    k_gemm<128, 64, 8, 4><<<gz, 256>>>(x, 128, nullptr, 0, W_gm, b_gm, zbuf, NN, 64);

    k_node<<<warp_blocks, 256>>>(x, attn_l, attn_r, W_gate);
    k_agg<<<warp_blocks, 256>>>(W_gate, b_gate, b_gat);

    dim3 gm((NN + 127) / 128, 1);
    k_gemm<128, 64, 8, 4><<<gm, 256>>>(x, 128, gated, 64, W_merge, b_merge, out, NN, 64);
}